// round 2
// baseline (speedup 1.0000x reference)
#include <cuda_runtime.h>
#include <cstdint>
#include <cstddef>

// Problem constants
#define NEXP 8
#define TOPK 2
#define DIM 1024
#define DFF 4096
#define NTOK 16384          // B*S = 4*4096
#define CAP  16384          // per-expert capacity (worst case all tokens)
#define RTOT (NTOK * TOPK)  // 32768 total expert-rows

// ---------------- scratch (static device globals; no runtime alloc) ----------
__device__ int   g_cnt[NEXP];
__device__ int   g_off[NEXP];
__device__ int   g_tok[NEXP * CAP];
__device__ int   g_dst[NEXP * CAP];
__device__ float g_wtl[NEXP * CAP];
__device__ float g_H[(size_t)RTOT * DFF];   // 512 MB hidden scratch
__device__ float g_O[(size_t)RTOT * DIM];   // 128 MB per-slot outputs

// ---------------- helpers ----------------------------------------------------
__device__ __forceinline__ float tf32r(float f) {
    unsigned u;
    asm volatile("cvt.rna.tf32.f32 %0, %1;" : "=r"(u) : "f"(f));
    return __uint_as_float(u);
}

__device__ __forceinline__ void mma_tf32(float c[4], const unsigned a[4], const unsigned b[2]) {
    asm volatile(
        "mma.sync.aligned.m16n8k8.row.col.f32.tf32.tf32.f32 "
        "{%0,%1,%2,%3}, {%4,%5,%6,%7}, {%8,%9}, {%0,%1,%2,%3};\n"
        : "+f"(c[0]), "+f"(c[1]), "+f"(c[2]), "+f"(c[3])
        : "r"(a[0]), "r"(a[1]), "r"(a[2]), "r"(a[3]), "r"(b[0]), "r"(b[1]));
}

// ---------------- kernel 0: zero counters ------------------------------------
__global__ void zero_kernel() {
    if (threadIdx.x < NEXP) g_cnt[threadIdx.x] = 0;
}

// ---------------- kernel 1: routing (one warp per token) ----------------------
__global__ void route_kernel(const float* __restrict__ x, const float* __restrict__ gw) {
    __shared__ float s_gw[NEXP * DIM];   // 32 KB
    int tid = threadIdx.x;
    for (int i = tid; i < NEXP * DIM; i += blockDim.x) s_gw[i] = gw[i];
    __syncthreads();

    int warp = tid >> 5, lane = tid & 31;
    int t = blockIdx.x * (blockDim.x >> 5) + warp;
    if (t >= NTOK) return;

    const float* xr = x + (size_t)t * DIM;
    float xv[32];
#pragma unroll
    for (int i = 0; i < 32; i++) xv[i] = xr[i * 32 + lane];

    float logit[NEXP];
#pragma unroll
    for (int e = 0; e < NEXP; e++) {
        float acc = 0.f;
#pragma unroll
        for (int i = 0; i < 32; i++) acc += xv[i] * s_gw[e * DIM + i * 32 + lane];
#pragma unroll
        for (int o = 16; o; o >>= 1) acc += __shfl_xor_sync(0xffffffffu, acc, o);
        logit[e] = acc;
    }

    if (lane == 0) {
        // top-2, jax tie semantics: first occurrence of max wins
        int i0 = 0;
#pragma unroll
        for (int e = 1; e < NEXP; e++) if (logit[e] > logit[i0]) i0 = e;
        int i1 = (i0 == 0) ? 1 : 0;
#pragma unroll
        for (int e = 0; e < NEXP; e++) {
            if (e == i0 || e == i1) continue;
            if (logit[e] > logit[i1]) i1 = e;
        }
        float dd = logit[i1] - logit[i0];   // <= 0
        float ee = __expf(dd);
        float inv = 1.f / (1.f + ee);
        float w0 = inv, w1 = ee * inv;

        int p0 = atomicAdd(&g_cnt[i0], 1);
        g_tok[i0 * CAP + p0] = t;
        g_dst[i0 * CAP + p0] = t * 2;
        g_wtl[i0 * CAP + p0] = w0;
        int p1 = atomicAdd(&g_cnt[i1], 1);
        g_tok[i1 * CAP + p1] = t;
        g_dst[i1 * CAP + p1] = t * 2 + 1;
        g_wtl[i1 * CAP + p1] = w1;
    }
}

// ---------------- kernel 2: prefix offsets ------------------------------------
__global__ void prefix_kernel() {
    if (threadIdx.x == 0) {
        int s = 0;
#pragma unroll
        for (int e = 0; e < NEXP; e++) { g_off[e] = s; s += g_cnt[e]; }
    }
}

// ---------------- kernels 3/4: grouped GEMM (tf32 mma.sync) -------------------
// MODE 0: H[off+m] = silu(gather(x)[m] @ W1[e] + b1[e])   (KDIM=DIM,  NDIM=DFF)
// MODE 1: O[dst]   = (H[off+m] @ W2[e] + b2[e]) * wt      (KDIM=DFF,  NDIM=DIM)
template <int KDIM, int NDIM, int MODE>
__global__ void __launch_bounds__(256) ffn_gemm(const float* __restrict__ Ain,
                                                const float* __restrict__ Wall,
                                                const float* __restrict__ ball) {
    constexpr int BM = 128, BN = 128, BK = 32;
    constexpr int KT = KDIM / BK;

    int e = blockIdx.z;
    int cnt = g_cnt[e];
    int m0 = blockIdx.y * BM;
    if (m0 >= cnt) return;
    int n0 = blockIdx.x * BN;
    int off = g_off[e];

    const float* W = Wall + (size_t)e * KDIM * NDIM;
    const float* bias = ball + (size_t)e * NDIM;

    __shared__ float sA[BM][BK + 4];   // 18.4 KB, conflict-free frag reads
    __shared__ float sB[BK][BN + 4];   // 16.9 KB

    int tid = threadIdx.x;
    int warp = tid >> 5, lane = tid & 31;
    int wm = warp & 1, wn = warp >> 1;       // warps: 2 (M) x 4 (N)
    int group = lane >> 2, tig = lane & 3;

    // per-thread global staging pointers (4 float4 for A, 4 for B)
    const float* aptr[4];
    bool aval[4];
#pragma unroll
    for (int i = 0; i < 4; i++) {
        int f4 = tid + 256 * i;
        int r = f4 >> 3, c4 = f4 & 7;
        int m = m0 + r;
        aval[i] = (m < cnt);
        if (MODE == 0) {
            int tok = aval[i] ? g_tok[e * CAP + m] : 0;
            aptr[i] = Ain + (size_t)tok * KDIM + c4 * 4;
        } else {
            int gr = aval[i] ? (off + m) : 0;
            aptr[i] = g_H + (size_t)gr * KDIM + c4 * 4;
        }
    }
    const float* bptr[4];
#pragma unroll
    for (int i = 0; i < 4; i++) {
        int f4 = tid + 256 * i;
        int br = f4 >> 5, bc4 = f4 & 31;
        bptr[i] = W + (size_t)br * NDIM + n0 + bc4 * 4;
    }

    float acc[4][4][4];
#pragma unroll
    for (int mi = 0; mi < 4; mi++)
#pragma unroll
        for (int ni = 0; ni < 4; ni++)
#pragma unroll
            for (int r = 0; r < 4; r++) acc[mi][ni][r] = 0.f;

    float4 ra[4], rb[4];

    auto gload = [&](int kt) {
#pragma unroll
        for (int i = 0; i < 4; i++)
            ra[i] = aval[i] ? *(const float4*)(aptr[i] + (size_t)kt * BK)
                            : make_float4(0.f, 0.f, 0.f, 0.f);
#pragma unroll
        for (int i = 0; i < 4; i++)
            rb[i] = *(const float4*)(bptr[i] + (size_t)kt * BK * NDIM);
    };
    auto sstore = [&]() {
#pragma unroll
        for (int i = 0; i < 4; i++) {
            int f4 = tid + 256 * i;
            int r = f4 >> 3, c4 = f4 & 7;
            float4 v = ra[i];
            v.x = tf32r(v.x); v.y = tf32r(v.y); v.z = tf32r(v.z); v.w = tf32r(v.w);
            *(float4*)&sA[r][c4 * 4] = v;
        }
#pragma unroll
        for (int i = 0; i < 4; i++) {
            int f4 = tid + 256 * i;
            int br = f4 >> 5, bc4 = f4 & 31;
            float4 v = rb[i];
            v.x = tf32r(v.x); v.y = tf32r(v.y); v.z = tf32r(v.z); v.w = tf32r(v.w);
            *(float4*)&sB[br][bc4 * 4] = v;
        }
    };

    gload(0);
    sstore();
    __syncthreads();

    for (int kt = 0; kt < KT; kt++) {
        bool more = (kt + 1 < KT);
        if (more) gload(kt + 1);

#pragma unroll
        for (int ks = 0; ks < 4; ks++) {
            int kk = ks * 8;
            unsigned af[4][4], bf[4][2];
#pragma unroll
            for (int mi = 0; mi < 4; mi++) {
                int r = wm * 64 + mi * 16 + group;
                af[mi][0] = __float_as_uint(sA[r][kk + tig]);
                af[mi][1] = __float_as_uint(sA[r + 8][kk + tig]);
                af[mi][2] = __float_as_uint(sA[r][kk + tig + 4]);
                af[mi][3] = __float_as_uint(sA[r + 8][kk + tig + 4]);
            }
#pragma unroll
            for (int ni = 0; ni < 4; ni++) {
                int c = wn * 32 + ni * 8 + group;
                bf[ni][0] = __float_as_uint(sB[kk + tig][c]);
                bf[ni][1] = __float_as_uint(sB[kk + tig + 4][c]);
            }
#pragma unroll
            for (int mi = 0; mi < 4; mi++)
#pragma unroll
                for (int ni = 0; ni < 4; ni++)
                    mma_tf32(acc[mi][ni], af[mi], bf[ni]);
        }

        __syncthreads();
        if (more) {
            sstore();
            __syncthreads();
        }
    }

    // epilogue
#pragma unroll
    for (int mi = 0; mi < 4; mi++) {
#pragma unroll
        for (int half = 0; half < 2; half++) {
            int m = m0 + wm * 64 + mi * 16 + group + half * 8;
            if (m >= cnt) continue;
            if (MODE == 0) {
                size_t rowbase = (size_t)(off + m) * NDIM;
#pragma unroll
                for (int ni = 0; ni < 4; ni++) {
                    int c = n0 + wn * 32 + ni * 8 + tig * 2;
                    float v0 = acc[mi][ni][half * 2 + 0] + bias[c];
                    float v1 = acc[mi][ni][half * 2 + 1] + bias[c + 1];
                    g_H[rowbase + c]     = v0 / (1.f + __expf(-v0));
                    g_H[rowbase + c + 1] = v1 / (1.f + __expf(-v1));
                }
            } else {
                int dst = g_dst[e * CAP + m];
                float w = g_wtl[e * CAP + m];
                size_t rowbase = (size_t)dst * NDIM;
#pragma unroll
                for (int ni = 0; ni < 4; ni++) {
                    int c = n0 + wn * 32 + ni * 8 + tig * 2;
                    g_O[rowbase + c]     = (acc[mi][ni][half * 2 + 0] + bias[c]) * w;
                    g_O[rowbase + c + 1] = (acc[mi][ni][half * 2 + 1] + bias[c + 1]) * w;
                }
            }
        }
    }
}

// ---------------- kernel 5: combine the two slots -----------------------------
__global__ void combine_kernel(float4* __restrict__ out) {
    int i = blockIdx.x * 256 + threadIdx.x;       // one float4 each; exact cover
    int t = i >> 8;                               // DIM/4 = 256 float4 per token
    int d4 = i & 255;
    const float4* O4 = (const float4*)g_O;
    float4 a = O4[(size_t)(2 * t) * 256 + d4];
    float4 b = O4[(size_t)(2 * t + 1) * 256 + d4];
    out[i] = make_float4(a.x + b.x, a.y + b.y, a.z + b.z, a.w + b.w);
}

// ---------------- launch ------------------------------------------------------
extern "C" void kernel_launch(void* const* d_in, const int* in_sizes, int n_in,
                              void* d_out, int out_size) {
    const float* x  = (const float*)d_in[0];
    const float* gw = (const float*)d_in[1];
    const float* W1 = (const float*)d_in[2];
    const float* b1 = (const float*)d_in[3];
    const float* W2 = (const float*)d_in[4];
    const float* b2 = (const float*)d_in[5];
    float* out = (float*)d_out;

    zero_kernel<<<1, 32>>>();
    route_kernel<<<NTOK / 8, 256>>>(x, gw);
    prefix_kernel<<<1, 32>>>();
    ffn_gemm<DIM, DFF, 0><<<dim3(DFF / 128, CAP / 128, NEXP), 256>>>(x, W1, b1);
    ffn_gemm<DFF, DIM, 1><<<dim3(DIM / 128, CAP / 128, NEXP), 256>>>(nullptr, W2, b2);
    combine_kernel<<<(NTOK * (DIM / 4)) / 256, 256>>>((float4*)out);
}